// round 1
// baseline (speedup 1.0000x reference)
#include <cuda_runtime.h>
#include <math.h>

// Problem constants
#define SS 128          // sections
#define QQ 64           // questions per section
#define PP 64           // sentences per section
#define DD 256          // embedding dim
#define NROW (SS*QQ)    // 8192 question rows
#define NE   (SS*PP)    // 8192 sentence rows
#define INV_TEMP (1.0f/0.07f)
#define LAM 0.1f
#define SEGS 8          // m-dimension segments for big GEMM
#define COLT 128        // col tile
#define KC 64           // k chunk

// -------- scratch (device globals; no allocations allowed) --------
__device__ float g_qnt[DD*NROW];   // normalized questions, k-major [k][row]
__device__ float g_snt[DD*NE];     // normalized sentences,  k-major [k][row]
__device__ float g_stnt[DD*SS];    // normalized section titles, k-major [k][s]
__device__ float g_pos[SS*QQ*PP];  // exp(pos_sim/T)
__device__ float g_Epart[SEGS*NROW];
__device__ float g_qs_part[SS];
__device__ float g_den_part[SS*SS]; // [t-block][s]
__device__ float g_num_part[SS];

// ================= normalize (+ transpose to k-major) =================
__global__ void norm_kernel(const float* __restrict__ q_in,
                            const float* __restrict__ s_in,
                            const float* __restrict__ st_in) {
    int row = blockIdx.x;
    const float* src; float* dst; int W, col;
    if (row < NROW)           { src = q_in  + (size_t)row*DD;        dst = g_qnt;  W = NROW; col = row; }
    else if (row < 2*NROW)    { int r = row - NROW;   src = s_in  + (size_t)r*DD; dst = g_snt;  W = NE;  col = r; }
    else                      { int r = row - 2*NROW; src = st_in + (size_t)r*DD; dst = g_stnt; W = SS;  col = r; }

    int tid = threadIdx.x; // 64 threads, each 4 elems
    float4 v = ((const float4*)src)[tid];
    float ss = v.x*v.x + v.y*v.y + v.z*v.z + v.w*v.w;
    #pragma unroll
    for (int o = 16; o > 0; o >>= 1) ss += __shfl_down_sync(0xffffffffu, ss, o);
    __shared__ float sh[2];
    if ((tid & 31) == 0) sh[tid >> 5] = ss;
    __syncthreads();
    float total = sh[0] + sh[1];
    float sc = 1.0f / fmaxf(sqrtf(total), 1e-12f);
    int k = tid * 4;
    dst[(size_t)(k+0)*W + col] = v.x * sc;
    dst[(size_t)(k+1)*W + col] = v.y * sc;
    dst[(size_t)(k+2)*W + col] = v.z * sc;
    dst[(size_t)(k+3)*W + col] = v.w * sc;
}

// ================= big fused GEMM + exp + row-sum =================
// block (s, seg): rows = questions of section s (64), cols = 1024 sentences.
// Computes partial total_exp into g_Epart and stores diagonal pos block.
extern __shared__ float smemB[];
__global__ void __launch_bounds__(256, 2) qs_gemm_kernel() {
    int s   = blockIdx.x;
    int seg = blockIdx.y;
    float* As = smemB;               // [256][64]
    float* Bs = smemB + DD*64;       // [64][128]
    int tid = threadIdx.x;
    int tr = tid & 15;               // row group (4 rows)
    int tc = tid >> 4;               // col group (8 cols)

    // load A tile (all K), coalesced, conflict-free (source is k-major)
    #pragma unroll
    for (int i = 0; i < 16; i++) {
        int slot = i*256 + tid;           // 4096 float4
        int r4 = slot & 15, k = slot >> 4;
        *(float4*)(As + k*64 + r4*4) =
            *(const float4*)(g_qnt + (size_t)k*NROW + s*64 + r4*4);
    }

    float rs[4] = {0.f, 0.f, 0.f, 0.f};
    const int d0 = s * 64;

    for (int ct = 0; ct < 8; ct++) {
        int c0 = seg*1024 + ct*COLT;
        float acc[4][8];
        #pragma unroll
        for (int i = 0; i < 4; i++)
            #pragma unroll
            for (int j = 0; j < 8; j++) acc[i][j] = 0.f;

        for (int kc = 0; kc < 4; kc++) {
            __syncthreads();
            #pragma unroll
            for (int i = 0; i < 8; i++) {
                int slot = i*256 + tid;        // 2048 float4
                int c4 = slot & 31, k = slot >> 5;
                *(float4*)(Bs + k*COLT + c4*4) =
                    *(const float4*)(g_snt + (size_t)(kc*KC + k)*NE + c0 + c4*4);
            }
            __syncthreads();
            #pragma unroll 8
            for (int kk = 0; kk < KC; kk++) {
                const float4 a  = *(const float4*)(As + (kc*KC + kk)*64 + tr*4);
                const float4 b0 = *(const float4*)(Bs + kk*COLT + tc*8);
                const float4 b1 = *(const float4*)(Bs + kk*COLT + tc*8 + 4);
                float av[4] = {a.x, a.y, a.z, a.w};
                float bv[8] = {b0.x, b0.y, b0.z, b0.w, b1.x, b1.y, b1.z, b1.w};
                #pragma unroll
                for (int i = 0; i < 4; i++)
                    #pragma unroll
                    for (int j = 0; j < 8; j++)
                        acc[i][j] = fmaf(av[i], bv[j], acc[i][j]);
            }
        }

        // epilogue: exp, row-sum accumulate, store pos block if diagonal
        bool diag = (d0 >= c0) && (d0 < c0 + COLT);
        int pbase = d0 - c0;
        #pragma unroll
        for (int i = 0; i < 4; i++) {
            #pragma unroll
            for (int j = 0; j < 8; j++) {
                float e = __expf(acc[i][j] * INV_TEMP);
                rs[i] += e;
                int c = tc*8 + j;
                if (diag && (unsigned)(c - pbase) < 64u)
                    g_pos[(size_t)s*4096 + (tr*4 + i)*64 + (c - pbase)] = e;
            }
        }
    }

    // reduce row sums across threads -> Epart
    __shared__ float rowsum[64];
    if (tid < 64) rowsum[tid] = 0.f;
    __syncthreads();
    #pragma unroll
    for (int i = 0; i < 4; i++) atomicAdd(&rowsum[tr*4 + i], rs[i]);
    __syncthreads();
    if (tid < 64) g_Epart[seg*NROW + s*64 + tid] = rowsum[tid];
}

// ================= sq_loss GEMM: one block per question-section t =================
__global__ void __launch_bounds__(256, 1) sq_kernel() {
    extern __shared__ float sm[];
    float* Ss = sm;              // stn k-major [256][128]
    float* Qs = sm + DD*SS;      // this block's 64 q rows [256][64]
    int b = blockIdx.x, tid = threadIdx.x;
    int tr = tid & 15;           // rows (4)
    int ts = tid >> 4;           // s group (8)

    #pragma unroll
    for (int i = 0; i < 32; i++) {   // 8192 float4
        int slot = i*256 + tid;
        ((float4*)Ss)[slot] = ((const float4*)g_stnt)[slot];
    }
    #pragma unroll
    for (int i = 0; i < 16; i++) {   // 4096 float4
        int slot = i*256 + tid;
        int r4 = slot & 15, k = slot >> 4;
        *(float4*)(Qs + k*64 + r4*4) =
            *(const float4*)(g_qnt + (size_t)k*NROW + b*64 + r4*4);
    }
    __syncthreads();

    float acc[8][4];
    #pragma unroll
    for (int j = 0; j < 8; j++)
        #pragma unroll
        for (int i = 0; i < 4; i++) acc[j][i] = 0.f;

    #pragma unroll 8
    for (int k = 0; k < DD; k++) {
        const float4 qv = *(const float4*)(Qs + k*64 + tr*4);
        const float4 s0 = *(const float4*)(Ss + k*128 + ts*8);
        const float4 s1 = *(const float4*)(Ss + k*128 + ts*8 + 4);
        float rvals[4] = {qv.x, qv.y, qv.z, qv.w};
        float svals[8] = {s0.x, s0.y, s0.z, s0.w, s1.x, s1.y, s1.z, s1.w};
        #pragma unroll
        for (int j = 0; j < 8; j++)
            #pragma unroll
            for (int i = 0; i < 4; i++)
                acc[j][i] = fmaf(svals[j], rvals[i], acc[j][i]);
    }

    #pragma unroll
    for (int j = 0; j < 8; j++) {
        float v = 0.f;
        #pragma unroll
        for (int i = 0; i < 4; i++) v += __expf(acc[j][i] * INV_TEMP);
        #pragma unroll
        for (int o = 8; o > 0; o >>= 1) v += __shfl_down_sync(0xffffffffu, v, o, 16);
        if (tr == 0) {
            int sidx = ts*8 + j;
            g_den_part[b*SS + sidx] = v;
            if (sidx == b) g_num_part[b] = v;
        }
    }
}

// ================= qs loss assembly: one block per section =================
__global__ void qs_loss_kernel() {
    int s = blockIdx.x, tid = threadIdx.x;   // 256 threads
    __shared__ float own[64], Es[64], partial[256];
    const float* pos = g_pos + (size_t)s*4096;

    int q = tid >> 2, t4 = tid & 3;
    float p4 = 0.f;
    #pragma unroll
    for (int pp = 0; pp < 16; pp++) p4 += pos[q*64 + t4*16 + pp];
    partial[tid] = p4;
    __syncthreads();
    if (tid < 64) {
        own[tid] = partial[tid*4] + partial[tid*4+1] + partial[tid*4+2] + partial[tid*4+3];
        float e = 0.f;
        #pragma unroll
        for (int g = 0; g < SEGS; g++) e += g_Epart[g*NROW + s*64 + tid];
        Es[tid] = e;
    }
    __syncthreads();

    const float term2 = __expf(-INV_TEMP) * (float)(NE - 1);
    float l = 0.f;
    #pragma unroll
    for (int it = 0; it < 16; it++) {
        int idx = it*256 + tid;
        int qq = idx >> 6;
        float pv = pos[idx];
        float neg = Es[qq] - own[qq];
        float t1 = fmaf(-LAM, pv, neg * (1.0f/(1.0f - LAM)));
        float Ng = fmaxf(fmaxf(t1, term2), 1e-8f);
        l += logf((pv + Ng) / pv);            // = -log(pos/(pos+Ng))
    }
    partial[tid] = l;
    __syncthreads();
    for (int o = 128; o > 0; o >>= 1) {
        if (tid < o) partial[tid] += partial[tid + o];
        __syncthreads();
    }
    if (tid == 0) g_qs_part[s] = partial[0];
}

// ================= final reduce =================
__global__ void final_kernel(float* out) {
    int tid = threadIdx.x; // 128
    float den = 0.f;
    #pragma unroll 8
    for (int bb = 0; bb < SS; bb++) den += g_den_part[bb*SS + tid];
    // sq term: -log(num/den) = log(den/num); at_loss = -log(x/x) = 0
    float v = logf(den / g_num_part[tid]) + g_qs_part[tid];
    __shared__ float sh[128];
    sh[tid] = v;
    __syncthreads();
    for (int o = 64; o > 0; o >>= 1) {
        if (tid < o) sh[tid] += sh[tid + o];
        __syncthreads();
    }
    if (tid == 0) out[0] = sh[0];
}

// ================= launch =================
extern "C" void kernel_launch(void* const* d_in, const int* in_sizes, int n_in,
                              void* d_out, int out_size) {
    (void)in_sizes; (void)n_in; (void)out_size;
    const float* art  = (const float*)d_in[0]; (void)art; // at_loss == 0 exactly
    const float* sec  = (const float*)d_in[1];
    const float* ques = (const float*)d_in[2];
    const float* sent = (const float*)d_in[3];

    cudaFuncSetAttribute(qs_gemm_kernel, cudaFuncAttributeMaxDynamicSharedMemorySize, 98304);
    cudaFuncSetAttribute(sq_kernel,      cudaFuncAttributeMaxDynamicSharedMemorySize, 196608);

    norm_kernel<<<2*NROW + SS, 64>>>(ques, sent, sec);
    dim3 gB(SS, SEGS);
    qs_gemm_kernel<<<gB, 256, 98304>>>();
    sq_kernel<<<SS, 256, 196608>>>();
    qs_loss_kernel<<<SS, 256>>>();
    final_kernel<<<1, 128>>>((float*)d_out);
}

// round 3
// speedup vs baseline: 4.8252x; 4.8252x over previous
#include <cuda_runtime.h>
#include <cuda_bf16.h>
#include <cstdint>
#include <math.h>

// Problem constants
#define SS 128
#define QQ 64
#define PP 64
#define DD 256
#define NROW (SS*QQ)
#define NE   (SS*PP)
#define INV_TEMP (1.0f/0.07f)
#define LAM 0.1f
#define NPART 128        // col partials = 64 col-blocks * 2 warp-halves

// -------- scratch (device globals) --------
__device__ float g_qnt[DD*NROW];          // normalized questions, k-major fp32 (for sq)
__device__ float g_stnt[DD*SS];           // normalized section titles, k-major fp32
__device__ __nv_bfloat16 g_qh[NROW*DD];   // normalized questions, row-major bf16
__device__ __nv_bfloat16 g_sh[NE*DD];     // normalized sentences, row-major bf16
__device__ float g_pos[SS*QQ*PP];
__device__ float g_Epart[NPART*NROW];     // [p][row], every slot written once
__device__ float g_qs_part[SS];
__device__ float g_den_part[SS*SS];
__device__ float g_num_part[SS];

// ================= helpers =================
__device__ __forceinline__ uint32_t smem_u32(const void* p) {
    uint32_t a;
    asm("{ .reg .u64 t; cvta.to.shared.u64 t, %1; cvt.u32.u64 %0, t; }" : "=r"(a) : "l"(p));
    return a;
}
#define SW128(o) ((o) ^ (((o) >> 3) & 0x70))

__device__ __forceinline__ void cp16(uint32_t dst, const void* src) {
    asm volatile("cp.async.cg.shared.global [%0], [%1], 16;" :: "r"(dst), "l"(src) : "memory");
}
#define CP_COMMIT() asm volatile("cp.async.commit_group;" ::: "memory")

__device__ __forceinline__ void ldsm4(uint32_t* r, uint32_t addr) {
    asm volatile("ldmatrix.sync.aligned.m8n8.x4.shared.b16 {%0,%1,%2,%3}, [%4];"
        : "=r"(r[0]), "=r"(r[1]), "=r"(r[2]), "=r"(r[3]) : "r"(addr));
}
__device__ __forceinline__ void mma16816(float* c, const uint32_t* a, const uint32_t* b) {
    asm volatile(
        "mma.sync.aligned.m16n8k16.row.col.f32.bf16.bf16.f32 "
        "{%0,%1,%2,%3}, {%4,%5,%6,%7}, {%8,%9}, {%0,%1,%2,%3};"
        : "+f"(c[0]), "+f"(c[1]), "+f"(c[2]), "+f"(c[3])
        : "r"(a[0]), "r"(a[1]), "r"(a[2]), "r"(a[3]), "r"(b[0]), "r"(b[1]));
}

// ================= normalize =================
__global__ void norm_kernel(const float* __restrict__ q_in,
                            const float* __restrict__ s_in,
                            const float* __restrict__ st_in) {
    int row = blockIdx.x;
    int tid = threadIdx.x; // 64 threads, 4 elems each
    const float* src;
    int kind, col;
    if (row < NROW)        { src = q_in  + (size_t)row * DD; kind = 0; col = row; }
    else if (row < 2*NROW) { col = row - NROW;  src = s_in  + (size_t)col * DD; kind = 1; }
    else                   { col = row - 2*NROW; src = st_in + (size_t)col * DD; kind = 2; }

    float4 v = ((const float4*)src)[tid];
    float ss = v.x*v.x + v.y*v.y + v.z*v.z + v.w*v.w;
    #pragma unroll
    for (int o = 16; o > 0; o >>= 1) ss += __shfl_down_sync(0xffffffffu, ss, o);
    __shared__ float sh[2];
    if ((tid & 31) == 0) sh[tid >> 5] = ss;
    __syncthreads();
    float sc = 1.0f / fmaxf(sqrtf(sh[0] + sh[1]), 1e-12f);
    float a = v.x*sc, b = v.y*sc, c = v.z*sc, d = v.w*sc;
    int k = tid * 4;
    if (kind == 0) {
        g_qnt[(size_t)(k+0)*NROW + col] = a;
        g_qnt[(size_t)(k+1)*NROW + col] = b;
        g_qnt[(size_t)(k+2)*NROW + col] = c;
        g_qnt[(size_t)(k+3)*NROW + col] = d;
        __nv_bfloat162* dst = (__nv_bfloat162*)(g_qh + (size_t)col*DD + k);
        dst[0] = __nv_bfloat162(__float2bfloat16(a), __float2bfloat16(b));
        dst[1] = __nv_bfloat162(__float2bfloat16(c), __float2bfloat16(d));
    } else if (kind == 1) {
        __nv_bfloat162* dst = (__nv_bfloat162*)(g_sh + (size_t)col*DD + k);
        dst[0] = __nv_bfloat162(__float2bfloat16(a), __float2bfloat16(b));
        dst[1] = __nv_bfloat162(__float2bfloat16(c), __float2bfloat16(d));
    } else {
        g_stnt[(size_t)(k+0)*SS + col] = a;
        g_stnt[(size_t)(k+1)*SS + col] = b;
        g_stnt[(size_t)(k+2)*SS + col] = c;
        g_stnt[(size_t)(k+3)*SS + col] = d;
    }
}

// ================= qs GEMM via HMMA (bf16, fused exp + rowsum) =================
// grid (64, 64): block tile 128(M) x 128(N); K=256 in 4 chunks of 64.
// 8 warps in 4(M) x 2(N); warp tile 32 x 64.
// smem: 2 bufs x (A 16KB + B 16KB) = 64KB dynamic.
#define SMEM_QS 65536

__device__ __forceinline__ void load_tiles(uint32_t su, int buf, int bm, int bn,
                                           int kc, int tid) {
    const char* abase = (const char*)g_qh + (size_t)bm*128*512 + kc*128;
    const char* bbase = (const char*)g_sh + (size_t)bn*128*512 + kc*128;
    uint32_t da = su + buf*32768;
    uint32_t db = da + 16384;
    #pragma unroll
    for (int i = 0; i < 4; i++) {
        int idx = i*256 + tid;
        int row = idx >> 3, c16 = (idx & 7)*16;
        cp16(da + SW128(row*128 + c16), abase + (size_t)row*512 + c16);
        cp16(db + SW128(row*128 + c16), bbase + (size_t)row*512 + c16);
    }
}

__global__ void __launch_bounds__(256) qs_mma_kernel() {
    extern __shared__ char smem[];
    const uint32_t su = smem_u32(smem);
    const int tid = threadIdx.x;
    const int lane = tid & 31, wid = tid >> 5;
    const int wm = wid >> 1, wn = wid & 1;
    const int bm = blockIdx.x, bn = blockIdx.y;

    float acc[2][8][4];
    #pragma unroll
    for (int mt = 0; mt < 2; mt++)
        #pragma unroll
        for (int nt = 0; nt < 8; nt++)
            #pragma unroll
            for (int i = 0; i < 4; i++) acc[mt][nt][i] = 0.f;

    load_tiles(su, 0, bm, bn, 0, tid); CP_COMMIT();
    load_tiles(su, 1, bm, bn, 1, tid); CP_COMMIT();

    // precomputed per-lane ldmatrix address components
    const int arow = wm*32 + (lane & 15);          // + mt*16
    const int aoff = (lane >> 4) * 16;             // + kk*32
    const int brow = wn*64 + (lane & 7) + ((lane >> 4) & 1) * 8;  // + np*16
    const int boff = ((lane >> 3) & 1) * 16;       // + kk*32

    #pragma unroll
    for (int kc = 0; kc < 4; kc++) {
        if (kc < 2) asm volatile("cp.async.wait_group 1;" ::: "memory");
        else if (kc == 2) asm volatile("cp.async.wait_group 1;" ::: "memory");
        else asm volatile("cp.async.wait_group 0;" ::: "memory");
        __syncthreads();

        const uint32_t as = su + (kc & 1)*32768;
        const uint32_t bs = as + 16384;
        #pragma unroll
        for (int kk = 0; kk < 4; kk++) {
            uint32_t a[2][4], b[4][4];
            #pragma unroll
            for (int mt = 0; mt < 2; mt++)
                ldsm4(a[mt], as + SW128((arow + mt*16)*128 + kk*32 + aoff));
            #pragma unroll
            for (int np = 0; np < 4; np++)
                ldsm4(b[np], bs + SW128((brow + np*16)*128 + kk*32 + boff));
            #pragma unroll
            for (int mt = 0; mt < 2; mt++)
                #pragma unroll
                for (int nt = 0; nt < 8; nt++)
                    mma16816(acc[mt][nt], a[mt], b[nt >> 1] + (nt & 1)*2);
        }
        __syncthreads();
        if (kc + 2 < 4) { load_tiles(su, kc & 1, bm, bn, kc + 2, tid); CP_COMMIT(); }
    }

    // ---- epilogue: exp, pos store (diag), deterministic row partials ----
    const bool diag = (bm == bn) && ((wm >> 1) == wn);
    const int sect = bm*2 + wn;                       // valid when diag
    const int lr = (wm & 1)*32 + (lane >> 2);         // local row base (&63), + mt*16, +8
    float rsum[2][2] = {{0.f,0.f},{0.f,0.f}};

    #pragma unroll
    for (int mt = 0; mt < 2; mt++) {
        #pragma unroll
        for (int nt = 0; nt < 8; nt++) {
            float e0 = __expf(acc[mt][nt][0] * INV_TEMP);
            float e1 = __expf(acc[mt][nt][1] * INV_TEMP);
            float e2 = __expf(acc[mt][nt][2] * INV_TEMP);
            float e3 = __expf(acc[mt][nt][3] * INV_TEMP);
            rsum[mt][0] += e0 + e1;
            rsum[mt][1] += e2 + e3;
            if (diag) {
                int lcol = nt*8 + (lane & 3)*2;
                float2* p0 = (float2*)(g_pos + (size_t)sect*4096 + (lr + mt*16)*64 + lcol);
                float2* p1 = (float2*)(g_pos + (size_t)sect*4096 + (lr + mt*16 + 8)*64 + lcol);
                *p0 = make_float2(e0, e1);
                *p1 = make_float2(e2, e3);
            }
        }
    }
    const int part = bn*2 + wn;
    #pragma unroll
    for (int mt = 0; mt < 2; mt++) {
        #pragma unroll
        for (int rr = 0; rr < 2; rr++) {
            float v = rsum[mt][rr];
            v += __shfl_xor_sync(0xffffffffu, v, 1);
            v += __shfl_xor_sync(0xffffffffu, v, 2);
            if ((lane & 3) == 0)
                g_Epart[(size_t)part*NROW + bm*128 + wm*32 + mt*16 + rr*8 + (lane >> 2)] = v;
        }
    }
}

// ================= sq_loss GEMM (fp32 scalar, small) =================
__global__ void __launch_bounds__(256, 1) sq_kernel() {
    extern __shared__ float sm[];
    float* Ssm = sm;            // stn k-major [256][128]
    float* Qs = sm + DD*SS;     // 64 q rows k-major [256][64]
    int b = blockIdx.x, tid = threadIdx.x;
    int tr = tid & 15;
    int ts = tid >> 4;

    #pragma unroll
    for (int i = 0; i < 32; i++) {
        int slot = i*256 + tid;
        ((float4*)Ssm)[slot] = ((const float4*)g_stnt)[slot];
    }
    #pragma unroll
    for (int i = 0; i < 16; i++) {
        int slot = i*256 + tid;
        int r4 = slot & 15, k = slot >> 4;
        *(float4*)(Qs + k*64 + r4*4) =
            *(const float4*)(g_qnt + (size_t)k*NROW + b*64 + r4*4);
    }
    __syncthreads();

    float acc[8][4];
    #pragma unroll
    for (int j = 0; j < 8; j++)
        #pragma unroll
        for (int i = 0; i < 4; i++) acc[j][i] = 0.f;

    #pragma unroll 8
    for (int k = 0; k < DD; k++) {
        const float4 qv = *(const float4*)(Qs + k*64 + tr*4);
        const float4 s0 = *(const float4*)(Ssm + k*128 + ts*8);
        const float4 s1 = *(const float4*)(Ssm + k*128 + ts*8 + 4);
        float rv[4] = {qv.x, qv.y, qv.z, qv.w};
        float sv[8] = {s0.x, s0.y, s0.z, s0.w, s1.x, s1.y, s1.z, s1.w};
        #pragma unroll
        for (int j = 0; j < 8; j++)
            #pragma unroll
            for (int i = 0; i < 4; i++)
                acc[j][i] = fmaf(sv[j], rv[i], acc[j][i]);
    }

    #pragma unroll
    for (int j = 0; j < 8; j++) {
        float v = 0.f;
        #pragma unroll
        for (int i = 0; i < 4; i++) v += __expf(acc[j][i] * INV_TEMP);
        #pragma unroll
        for (int o = 8; o > 0; o >>= 1) v += __shfl_down_sync(0xffffffffu, v, o, 16);
        if (tr == 0) {
            int sidx = ts*8 + j;
            g_den_part[b*SS + sidx] = v;
            if (sidx == b) g_num_part[b] = v;
        }
    }
}

// ================= qs loss assembly =================
__global__ void qs_loss_kernel() {
    int s = blockIdx.x, tid = threadIdx.x;   // 256 threads
    __shared__ float own[64], Es[64], partial[256];
    const float* pos = g_pos + (size_t)s*4096;

    int q = tid >> 2, t4 = tid & 3;
    float p4 = 0.f;
    #pragma unroll
    for (int pp = 0; pp < 16; pp++) p4 += pos[q*64 + t4*16 + pp];
    partial[tid] = p4;

    // E partial reduce: 256 threads cooperate, 64 rows x 4 lanes of 32 partials
    float ep = 0.f;
    int er = tid >> 2, el = tid & 3;
    #pragma unroll
    for (int p = 0; p < 32; p++)
        ep += g_Epart[(size_t)(el*32 + p)*NROW + s*64 + er];
    __shared__ float epart[256];
    epart[tid] = ep;
    __syncthreads();
    if (tid < 64) {
        own[tid] = partial[tid*4] + partial[tid*4+1] + partial[tid*4+2] + partial[tid*4+3];
        Es[tid] = epart[tid*4] + epart[tid*4+1] + epart[tid*4+2] + epart[tid*4+3];
    }
    __syncthreads();

    const float term2 = __expf(-INV_TEMP) * (float)(NE - 1);
    float lsum = 0.f;
    #pragma unroll
    for (int it = 0; it < 16; it++) {
        int idx = it*256 + tid;
        int qq = idx >> 6;
        float pv = pos[idx];
        float neg = Es[qq] - own[qq];
        float t1 = fmaf(-LAM, pv, neg * (1.0f/(1.0f - LAM)));
        float Ng = fmaxf(fmaxf(t1, term2), 1e-8f);
        lsum += logf((pv + Ng) / pv);
    }
    partial[tid] = lsum;
    __syncthreads();
    for (int o = 128; o > 0; o >>= 1) {
        if (tid < o) partial[tid] += partial[tid + o];
        __syncthreads();
    }
    if (tid == 0) g_qs_part[s] = partial[0];
}

// ================= final reduce =================
__global__ void final_kernel(float* out) {
    int tid = threadIdx.x; // 128
    float den = 0.f;
    #pragma unroll 8
    for (int bb = 0; bb < SS; bb++) den += g_den_part[bb*SS + tid];
    float v = logf(den / g_num_part[tid]) + g_qs_part[tid];
    __shared__ float sh[128];
    sh[tid] = v;
    __syncthreads();
    for (int o = 64; o > 0; o >>= 1) {
        if (tid < o) sh[tid] += sh[tid + o];
        __syncthreads();
    }
    if (tid == 0) out[0] = sh[0];
}

// ================= launch =================
extern "C" void kernel_launch(void* const* d_in, const int* in_sizes, int n_in,
                              void* d_out, int out_size) {
    (void)in_sizes; (void)n_in; (void)out_size;
    const float* sec  = (const float*)d_in[1];
    const float* ques = (const float*)d_in[2];
    const float* sent = (const float*)d_in[3];

    cudaFuncSetAttribute(qs_mma_kernel, cudaFuncAttributeMaxDynamicSharedMemorySize, SMEM_QS);
    cudaFuncSetAttribute(sq_kernel,     cudaFuncAttributeMaxDynamicSharedMemorySize, 196608);

    norm_kernel<<<2*NROW + SS, 64>>>(ques, sent, sec);
    dim3 g(64, 64);
    qs_mma_kernel<<<g, 256, SMEM_QS>>>();
    sq_kernel<<<SS, 256, 196608>>>();
    qs_loss_kernel<<<SS, 256>>>();
    final_kernel<<<1, 128>>>((float*)d_out);
}

// round 4
// speedup vs baseline: 5.3287x; 1.1043x over previous
#include <cuda_runtime.h>
#include <cuda_bf16.h>
#include <cstdint>
#include <math.h>

// Problem constants
#define SS 128
#define QQ 64
#define PP 64
#define DD 256
#define NROW (SS*QQ)
#define NE   (SS*PP)
#define INV_TEMP (1.0f/0.07f)
#define LAM 0.1f
#define NPART 64          // col partials for total_exp (one per col block)

// -------- scratch (device globals) --------
__device__ uint8_t g_qh8[NROW*DD];   // normalized questions, row-major e4m3
__device__ uint8_t g_sh8[NE*DD];     // normalized sentences,  row-major e4m3
__device__ uint8_t g_sth8[SS*DD];    // normalized section titles, row-major e4m3
__device__ float g_pos[SS*QQ*PP];
__device__ float g_Epart[NPART*NROW];  // [bn][row], each slot written once
__device__ float g_qs_part[SS];
__device__ float g_den_part[64*SS];    // [bm][s]
__device__ float g_num_part[SS];

// ================= helpers =================
__device__ __forceinline__ uint32_t smem_u32(const void* p) {
    uint32_t a;
    asm("{ .reg .u64 t; cvta.to.shared.u64 t, %1; cvt.u32.u64 %0, t; }" : "=r"(a) : "l"(p));
    return a;
}
#define SW128(o) ((o) ^ (((o) >> 3) & 0x70))

__device__ __forceinline__ void cp16(uint32_t dst, const void* src) {
    asm volatile("cp.async.cg.shared.global [%0], [%1], 16;" :: "r"(dst), "l"(src) : "memory");
}
#define CP_COMMIT() asm volatile("cp.async.commit_group;" ::: "memory")

__device__ __forceinline__ void ldsm4(uint32_t* r, uint32_t addr) {
    asm volatile("ldmatrix.sync.aligned.m8n8.x4.shared.b16 {%0,%1,%2,%3}, [%4];"
        : "=r"(r[0]), "=r"(r[1]), "=r"(r[2]), "=r"(r[3]) : "r"(addr));
}
__device__ __forceinline__ void mma16832(float* c, const uint32_t* a, const uint32_t* b) {
    asm volatile(
        "mma.sync.aligned.m16n8k32.row.col.f32.e4m3.e4m3.f32 "
        "{%0,%1,%2,%3}, {%4,%5,%6,%7}, {%8,%9}, {%0,%1,%2,%3};"
        : "+f"(c[0]), "+f"(c[1]), "+f"(c[2]), "+f"(c[3])
        : "r"(a[0]), "r"(a[1]), "r"(a[2]), "r"(a[3]), "r"(b[0]), "r"(b[1]));
}
__device__ __forceinline__ uint16_t f2e4m3x2(float hi, float lo) {
    uint16_t r;
    asm("cvt.rn.satfinite.e4m3x2.f32 %0, %1, %2;" : "=h"(r) : "f"(hi), "f"(lo));
    return r;
}

// ================= normalize -> fp8 =================
__global__ void norm_kernel(const float* __restrict__ q_in,
                            const float* __restrict__ s_in,
                            const float* __restrict__ st_in) {
    int row = blockIdx.x;
    int tid = threadIdx.x; // 64 threads, 4 elems each
    const float* src;
    uint8_t* dst;
    int col;
    if (row < NROW)        { col = row;          src = q_in  + (size_t)col * DD; dst = g_qh8; }
    else if (row < 2*NROW) { col = row - NROW;   src = s_in  + (size_t)col * DD; dst = g_sh8; }
    else                   { col = row - 2*NROW; src = st_in + (size_t)col * DD; dst = g_sth8; }

    float4 v = ((const float4*)src)[tid];
    float ss = v.x*v.x + v.y*v.y + v.z*v.z + v.w*v.w;
    #pragma unroll
    for (int o = 16; o > 0; o >>= 1) ss += __shfl_down_sync(0xffffffffu, ss, o);
    __shared__ float sh[2];
    if ((tid & 31) == 0) sh[tid >> 5] = ss;
    __syncthreads();
    float sc = 1.0f / fmaxf(sqrtf(sh[0] + sh[1]), 1e-12f);
    uint16_t lo = f2e4m3x2(v.y*sc, v.x*sc);
    uint16_t hi = f2e4m3x2(v.w*sc, v.z*sc);
    *(uint32_t*)(dst + (size_t)col*DD + tid*4) = (uint32_t)lo | ((uint32_t)hi << 16);
}

// ================= fused qs+sq GEMM via FP8 MMA =================
// grid (64, 65): block tile 128(M) x 128(N); K=256 fp8 in 2 chunks of 128B.
// bn < 64: sentence cols (qs path: exp + rowsum + diag pos)
// bn == 64: section-title cols (sq path: exp + colsum -> den/num)
// 8 warps in 4(M) x 2(N); warp tile 32 x 64.
// smem: 2 chunks x (A 16KB + B 16KB) = 64KB dynamic.
#define SMEM_QS 65536

__device__ __forceinline__ void load_tiles(uint32_t su, int bm, int bn, int kc, int tid) {
    const uint8_t* abase = g_qh8 + (size_t)bm*128*256 + kc*128;
    const uint8_t* bbase = (bn < 64) ? (g_sh8 + (size_t)bn*128*256 + kc*128)
                                     : (g_sth8 + kc*128);
    uint32_t da = su + kc*32768;
    uint32_t db = da + 16384;
    #pragma unroll
    for (int i = 0; i < 4; i++) {
        int idx = i*256 + tid;
        int row = idx >> 3, c16 = (idx & 7)*16;
        cp16(da + SW128(row*128 + c16), abase + (size_t)row*256 + c16);
        cp16(db + SW128(row*128 + c16), bbase + (size_t)row*256 + c16);
    }
}

__global__ void __launch_bounds__(256) qs_mma_kernel() {
    extern __shared__ char smem[];
    const uint32_t su = smem_u32(smem);
    float* fs = (float*)smem;
    const int tid = threadIdx.x;
    const int lane = tid & 31, wid = tid >> 5;
    const int wm = wid >> 1, wn = wid & 1;
    const int bm = blockIdx.x, bn = blockIdx.y;

    float acc[2][8][4];
    #pragma unroll
    for (int mt = 0; mt < 2; mt++)
        #pragma unroll
        for (int nt = 0; nt < 8; nt++)
            #pragma unroll
            for (int i = 0; i < 4; i++) acc[mt][nt][i] = 0.f;

    load_tiles(su, bm, bn, 0, tid); CP_COMMIT();
    load_tiles(su, bm, bn, 1, tid); CP_COMMIT();

    // per-lane ldmatrix address components (fp8 fragments, same tile order as bf16)
    const int arow = wm*32 + (lane & 15);                         // + mt*16
    const int aoff = (lane >> 4) * 16;                            // + kk*32
    const int brow = wn*64 + (lane & 7) + ((lane >> 4) & 1) * 8;  // + np*16
    const int boff = ((lane >> 3) & 1) * 16;                      // + kk*32

    #pragma unroll
    for (int kc = 0; kc < 2; kc++) {
        if (kc == 0) asm volatile("cp.async.wait_group 1;" ::: "memory");
        else         asm volatile("cp.async.wait_group 0;" ::: "memory");
        __syncthreads();
        const uint32_t as = su + kc*32768;
        const uint32_t bs = as + 16384;
        #pragma unroll
        for (int kk = 0; kk < 4; kk++) {
            uint32_t a[2][4], b[4][4];
            #pragma unroll
            for (int mt = 0; mt < 2; mt++)
                ldsm4(a[mt], as + SW128((arow + mt*16)*128 + kk*32 + aoff));
            #pragma unroll
            for (int np = 0; np < 4; np++)
                ldsm4(b[np], bs + SW128((brow + np*16)*128 + kk*32 + boff));
            #pragma unroll
            for (int mt = 0; mt < 2; mt++)
                #pragma unroll
                for (int nt = 0; nt < 8; nt++)
                    mma16832(acc[mt][nt], a[mt], b[nt >> 1] + (nt & 1)*2);
        }
    }
    __syncthreads();  // MMA done; smem reused as float scratch below

    if (bn < 64) {
        // ---- qs path: exp, diag pos store, deterministic row partials ----
        const bool diag = (bm == bn) && ((wm >> 1) == wn);
        const int sect = bm*2 + wn;
        const int lr = (wm & 1)*32 + (lane >> 2);
        float rsum[2][2] = {{0.f,0.f},{0.f,0.f}};

        #pragma unroll
        for (int mt = 0; mt < 2; mt++) {
            #pragma unroll
            for (int nt = 0; nt < 8; nt++) {
                float e0 = __expf(acc[mt][nt][0] * INV_TEMP);
                float e1 = __expf(acc[mt][nt][1] * INV_TEMP);
                float e2 = __expf(acc[mt][nt][2] * INV_TEMP);
                float e3 = __expf(acc[mt][nt][3] * INV_TEMP);
                rsum[mt][0] += e0 + e1;
                rsum[mt][1] += e2 + e3;
                if (diag) {
                    int lcol = nt*8 + (lane & 3)*2;
                    float2* p0 = (float2*)(g_pos + (size_t)sect*4096 + (lr + mt*16)*64 + lcol);
                    float2* p1 = (float2*)(g_pos + (size_t)sect*4096 + (lr + mt*16 + 8)*64 + lcol);
                    *p0 = make_float2(e0, e1);
                    *p1 = make_float2(e2, e3);
                }
            }
        }
        #pragma unroll
        for (int mt = 0; mt < 2; mt++) {
            #pragma unroll
            for (int rr = 0; rr < 2; rr++) {
                float v = rsum[mt][rr];
                v += __shfl_xor_sync(0xffffffffu, v, 1);
                v += __shfl_xor_sync(0xffffffffu, v, 2);
                if ((lane & 3) == 0)
                    fs[wn*128 + wm*32 + mt*16 + rr*8 + (lane >> 2)] = v;
            }
        }
        __syncthreads();
        if (tid < 128)
            g_Epart[(size_t)bn*NROW + bm*128 + tid] = fs[tid] + fs[128 + tid];
    } else {
        // ---- sq path: exp, column sums -> den_part / num_part ----
        // col = wn*64 + nt*8 + (lane&3)*2 + c01 ; rows of this warp: wm*32..+31
        #pragma unroll
        for (int nt = 0; nt < 8; nt++) {
            #pragma unroll
            for (int c01 = 0; c01 < 2; c01++) {
                float v = __expf(acc[0][nt][c01]     * INV_TEMP)
                        + __expf(acc[0][nt][c01 + 2] * INV_TEMP)
                        + __expf(acc[1][nt][c01]     * INV_TEMP)
                        + __expf(acc[1][nt][c01 + 2] * INV_TEMP);
                v += __shfl_xor_sync(0xffffffffu, v, 4);
                v += __shfl_xor_sync(0xffffffffu, v, 8);
                v += __shfl_xor_sync(0xffffffffu, v, 16);
                if (lane < 4)
                    fs[wm*128 + wn*64 + nt*8 + (lane & 3)*2 + c01] = v;
            }
        }
        __syncthreads();
        if (tid < 128) {
            float den = fs[tid] + fs[128 + tid] + fs[256 + tid] + fs[384 + tid];
            g_den_part[bm*SS + tid] = den;
        }
        if (tid < 2) {
            int s0 = 2*bm + tid;
            g_num_part[s0] = fs[2*tid*128 + s0] + fs[(2*tid + 1)*128 + s0];
        }
    }
}

// ================= qs loss assembly =================
__global__ void qs_loss_kernel() {
    int s = blockIdx.x, tid = threadIdx.x;   // 256 threads
    __shared__ float own[64], Es[64], partial[256], epart[256];
    const float* pos = g_pos + (size_t)s*4096;

    int q = tid >> 2, t4 = tid & 3;
    float p4 = 0.f;
    #pragma unroll
    for (int pp = 0; pp < 16; pp++) p4 += pos[q*64 + t4*16 + pp];
    partial[tid] = p4;

    float ep = 0.f;
    int er = tid >> 2, el = tid & 3;
    #pragma unroll
    for (int p = 0; p < 16; p++)
        ep += g_Epart[(size_t)(el*16 + p)*NROW + s*64 + er];
    epart[tid] = ep;
    __syncthreads();
    if (tid < 64) {
        own[tid] = partial[tid*4] + partial[tid*4+1] + partial[tid*4+2] + partial[tid*4+3];
        Es[tid]  = epart[tid*4] + epart[tid*4+1] + epart[tid*4+2] + epart[tid*4+3];
    }
    __syncthreads();

    const float term2 = __expf(-INV_TEMP) * (float)(NE - 1);
    float lsum = 0.f;
    #pragma unroll
    for (int it = 0; it < 16; it++) {
        int idx = it*256 + tid;
        int qq = idx >> 6;
        float pv = pos[idx];
        float neg = Es[qq] - own[qq];
        float t1 = fmaf(-LAM, pv, neg * (1.0f/(1.0f - LAM)));
        float Ng = fmaxf(fmaxf(t1, term2), 1e-8f);
        lsum += logf((pv + Ng) / pv);
    }
    partial[tid] = lsum;
    __syncthreads();
    for (int o = 128; o > 0; o >>= 1) {
        if (tid < o) partial[tid] += partial[tid + o];
        __syncthreads();
    }
    if (tid == 0) g_qs_part[s] = partial[0];
}

// ================= final reduce =================
__global__ void final_kernel(float* out) {
    int tid = threadIdx.x; // 128
    float den = 0.f;
    #pragma unroll 8
    for (int bm = 0; bm < 64; bm++) den += g_den_part[bm*SS + tid];
    float v = logf(den / g_num_part[tid]) + g_qs_part[tid];
    __shared__ float sh[128];
    sh[tid] = v;
    __syncthreads();
    for (int o = 64; o > 0; o >>= 1) {
        if (tid < o) sh[tid] += sh[tid + o];
        __syncthreads();
    }
    if (tid == 0) out[0] = sh[0];
}

// ================= launch =================
extern "C" void kernel_launch(void* const* d_in, const int* in_sizes, int n_in,
                              void* d_out, int out_size) {
    (void)in_sizes; (void)n_in; (void)out_size;
    const float* sec  = (const float*)d_in[1];
    const float* ques = (const float*)d_in[2];
    const float* sent = (const float*)d_in[3];

    cudaFuncSetAttribute(qs_mma_kernel, cudaFuncAttributeMaxDynamicSharedMemorySize, SMEM_QS);

    norm_kernel<<<2*NROW + SS, 64>>>(ques, sent, sec);
    dim3 g(64, 65);
    qs_mma_kernel<<<g, 256, SMEM_QS>>>();
    qs_loss_kernel<<<SS, 256>>>();
    final_kernel<<<1, 128>>>((float*)d_out);
}